// round 6
// baseline (speedup 1.0000x reference)
#include <cuda_runtime.h>

#define T_STEPS 8192
#define NN      2048
#define NCTA    128
#define ROWS    16      // neurons (w rows) per CTA
#define NTHR    256     // threads per CTA (8 warps)
#define CPT     8       // columns per thread (2048 / 256)

// Parity double-buffered conductance + one monotonic arrival counter.
__device__ float g_buf[2][NN];
__device__ unsigned int bar_ctr;   // total arrivals = NCTA * (steps completed)

__device__ __forceinline__ unsigned long long pack2(float lo, float hi) {
    unsigned long long r;
    asm("mov.b64 %0, {%1, %2};" : "=l"(r) : "f"(lo), "f"(hi));
    return r;
}
__device__ __forceinline__ void unpack2(unsigned long long p, float& lo, float& hi) {
    asm("mov.b64 {%0, %1}, %2;" : "=f"(lo), "=f"(hi) : "l"(p));
}
__device__ __forceinline__ unsigned long long fma2(unsigned long long a,
                                                   unsigned long long b,
                                                   unsigned long long c) {
    unsigned long long d;
    asm("fma.rn.f32x2 %0, %1, %2, %3;" : "=l"(d) : "l"(a), "l"(b), "l"(c));
    return d;
}
__device__ __forceinline__ unsigned long long mul2(unsigned long long a,
                                                   unsigned long long b) {
    unsigned long long d;
    asm("mul.rn.f32x2 %0, %1, %2;" : "=l"(d) : "l"(a), "l"(b));
    return d;
}

// Reset state so every graph replay is identical.
__global__ void lif_init_kernel(const float* __restrict__ g0) {
    int i = blockIdx.x * blockDim.x + threadIdx.x;
    if (i < NN) g_buf[0][i] = g0[i];
    if (i == 0) bar_ctr = 0;
}

__global__ void __launch_bounds__(NTHR, 1) lif_persistent_kernel(
    const float* __restrict__ x_in,    // [T, N]
    const float* __restrict__ w,       // [N, N] row-major
    const float* __restrict__ v_rest,  // [N]
    const float* __restrict__ tau_m,   // [N]
    const float* __restrict__ tau_g,   // [N]
    const float* __restrict__ pre_c_p, // [1]
    const float* __restrict__ post_c_p,// [1]
    const float* __restrict__ v0,      // [N]
    const float* __restrict__ g0,      // [N]
    float* __restrict__ out)           // [2, T, N]
{
    const int tid  = threadIdx.x;
    const int cta  = blockIdx.x;
    const int lane = tid & 31;
    const int warp = tid >> 5;
    const int row0 = cta * ROWS;
    const int col0 = tid * CPT;

    __shared__ float sh_part[2][8][ROWS];

    // ---- one-time: this CTA's 16 w rows in REGISTERS, packed as f32x2 ----
    unsigned long long wp2[ROWS][4];     // 64 x u64 = 128 fp32 regs
    #pragma unroll
    for (int r = 0; r < ROWS; r++) {
        const float4* wp = reinterpret_cast<const float4*>(
            w + (size_t)(row0 + r) * NN + col0);
        float4 a = wp[0], b = wp[1];
        wp2[r][0] = pack2(a.x, a.y);
        wp2[r][1] = pack2(a.z, a.w);
        wp2[r][2] = pack2(b.x, b.y);
        wp2[r][3] = pack2(b.z, b.w);
    }

    // ---- per-neuron state in the first 16 threads' registers ----
    const float pre_c  = pre_c_p[0];
    const float post_c = post_c_p[0];
    float my_v = 0.f, my_g = 0.f, my_vrest = 0.f, my_taum = 1.f, my_taug = 1.f;
    float x_next = 0.f;
    if (tid < ROWS) {
        int i = row0 + tid;
        my_v     = v0[i];
        my_g     = g0[i];
        my_vrest = v_rest[i];
        my_taum  = tau_m[i];
        my_taug  = tau_g[i];
        x_next   = __ldcs(&x_in[i]);   // prefetch x for t=0
    }
    __syncthreads();

    for (int t = 0; t < T_STEPS; t++) {
        const int par = t & 1;

        // ---- prefetch next step's x BEFORE the wait (hides under the spin) ----
        float x_cur = x_next;
        if (tid < ROWS && t + 1 < T_STEPS) {
            x_next = __ldcs(&x_in[(size_t)(t + 1) * NN + row0 + tid]);
        }

        // ---- wait until all CTAs finished step t-1 (counter = NCTA*t) ----
        if (t > 0) {
            if (tid == 0) {
                const unsigned target = (unsigned)(NCTA * t);
                unsigned c;
                do {
                    asm volatile("ld.acquire.gpu.global.u32 %0, [%1];"
                                 : "=r"(c) : "l"(&bar_ctr));
                } while (c < target);
            }
            __syncthreads();
        }

        // ---- load g for this step (L1-bypass; written by other SMs) ----
        unsigned long long gp2[4];
        {
            const float4 ga = __ldcg(reinterpret_cast<const float4*>(g_buf[par] + col0));
            const float4 gb = __ldcg(reinterpret_cast<const float4*>(g_buf[par] + col0 + 4));
            gp2[0] = pack2(ga.x, ga.y);
            gp2[1] = pack2(ga.z, ga.w);
            gp2[2] = pack2(gb.x, gb.y);
            gp2[3] = pack2(gb.z, gb.w);
        }

        // ---- matvec partials: 16 rows x 4 packed f32x2 FMAs per row ----
        float acc[ROWS];
        #pragma unroll
        for (int r = 0; r < ROWS; r++) {
            unsigned long long s2 = mul2(wp2[r][0], gp2[0]);
            s2 = fma2(wp2[r][1], gp2[1], s2);
            s2 = fma2(wp2[r][2], gp2[2], s2);
            s2 = fma2(wp2[r][3], gp2[3], s2);
            float lo, hi;
            unpack2(s2, lo, hi);
            acc[r] = lo + hi;
        }

        // ---- intra-warp folding reduction: 16 rows over 32 lanes, 16 SHFLs ----
        #pragma unroll
        for (int r = 0; r < 8; r++) {
            bool hi = (lane & 16) != 0;
            float send = hi ? acc[r] : acc[r + 8];
            float keep = hi ? acc[r + 8] : acc[r];
            acc[r] = keep + __shfl_xor_sync(0xffffffffu, send, 16);
        }
        #pragma unroll
        for (int r = 0; r < 4; r++) {
            bool hi = (lane & 8) != 0;
            float send = hi ? acc[r] : acc[r + 4];
            float keep = hi ? acc[r + 4] : acc[r];
            acc[r] = keep + __shfl_xor_sync(0xffffffffu, send, 8);
        }
        #pragma unroll
        for (int r = 0; r < 2; r++) {
            bool hi = (lane & 4) != 0;
            float send = hi ? acc[r] : acc[r + 2];
            float keep = hi ? acc[r + 2] : acc[r];
            acc[r] = keep + __shfl_xor_sync(0xffffffffu, send, 4);
        }
        {
            bool hi = (lane & 2) != 0;
            float send = hi ? acc[0] : acc[1];
            float keep = hi ? acc[1] : acc[0];
            acc[0] = keep + __shfl_xor_sync(0xffffffffu, send, 2);
        }
        acc[0] += __shfl_xor_sync(0xffffffffu, acc[0], 1);

        if ((lane & 1) == 0) sh_part[par][warp][lane >> 1] = acc[0];
        __syncthreads();

        // ---- LIF update + publish into next parity buffer ----
        float v_new = 0.f, soft = 0.f;
        if (tid < ROWS) {
            float y = 0.f;
            #pragma unroll
            for (int wq = 0; wq < 8; wq++) y += sh_part[par][wq][tid];
            y += x_cur;

            float I = post_c / (1.f + expf(-pre_c * y));
            float gd = my_g - my_g / my_taug;
            float v  = my_v + ((my_vrest - my_v) + I) / my_taum;
            soft = 1.f / (1.f + expf(-(v - 30.f)));
            bool spk = (v >= 30.f);
            v_new = spk ? my_vrest : v;
            float g_new = spk ? 1.f : gd;
            my_v = v_new;
            my_g = g_new;

            __stcg(&g_buf[(t + 1) & 1][row0 + tid], g_new);   // publish g
        }

        // Release: syncwarp orders warp 0's g stores before tid0's release-add
        // (PTX cumulativity) — no full membar drain on the critical path.
        if (warp == 0) {
            __syncwarp();
            if (lane == 0) {
                asm volatile("red.release.gpu.global.add.u32 [%0], %1;"
                             :: "l"(&bar_ctr), "r"(1u) : "memory");
            }
        }

        // Output traces AFTER the arrive — DRAM stores off the critical path.
        if (tid < ROWS) {
            int i = row0 + tid;
            __stcs(&out[(size_t)t * NN + i], v_new);
            __stcs(&out[(size_t)T_STEPS * NN + (size_t)t * NN + i], soft);
        }
    }
}

extern "C" void kernel_launch(void* const* d_in, const int* in_sizes, int n_in,
                              void* d_out, int out_size) {
    (void)in_sizes; (void)n_in; (void)out_size;
    const float* x_in   = (const float*)d_in[0];
    const float* w      = (const float*)d_in[1];
    const float* v_rest = (const float*)d_in[2];
    const float* tau_m  = (const float*)d_in[3];
    const float* tau_g  = (const float*)d_in[4];
    const float* pre_c  = (const float*)d_in[5];
    const float* post_c = (const float*)d_in[6];
    const float* v0     = (const float*)d_in[7];
    const float* g0     = (const float*)d_in[8];
    float* out = (float*)d_out;

    lif_init_kernel<<<(NN + 255) / 256, 256>>>(g0);
    lif_persistent_kernel<<<NCTA, NTHR>>>(x_in, w, v_rest, tau_m, tau_g,
                                          pre_c, post_c, v0, g0, out);
}

// round 7
// speedup vs baseline: 1.5012x; 1.5012x over previous
#include <cuda_runtime.h>

#define T_STEPS 8192
#define NN      2048
#define NCTA    128
#define ROWS    16      // neurons (w rows) per CTA
#define NTHR    256     // threads per CTA (8 warps)
#define CPT     8       // columns per thread (2048 / 256)

// Parity double-buffered conductance + one monotonic arrival counter.
__device__ float g_buf[2][NN];
__device__ unsigned int bar_ctr;   // total arrivals = NCTA * (steps completed)

__device__ __forceinline__ unsigned long long pack2(float lo, float hi) {
    unsigned long long r;
    asm("mov.b64 %0, {%1, %2};" : "=l"(r) : "f"(lo), "f"(hi));
    return r;
}
__device__ __forceinline__ void unpack2(unsigned long long p, float& lo, float& hi) {
    asm("mov.b64 {%0, %1}, %2;" : "=f"(lo), "=f"(hi) : "l"(p));
}
__device__ __forceinline__ unsigned long long fma2(unsigned long long a,
                                                   unsigned long long b,
                                                   unsigned long long c) {
    unsigned long long d;
    asm("fma.rn.f32x2 %0, %1, %2, %3;" : "=l"(d) : "l"(a), "l"(b), "l"(c));
    return d;
}
__device__ __forceinline__ unsigned long long mul2(unsigned long long a,
                                                   unsigned long long b) {
    unsigned long long d;
    asm("mul.rn.f32x2 %0, %1, %2;" : "=l"(d) : "l"(a), "l"(b));
    return d;
}

// Reset state so every graph replay is identical.
__global__ void lif_init_kernel(const float* __restrict__ g0) {
    int i = blockIdx.x * blockDim.x + threadIdx.x;
    if (i < NN) g_buf[0][i] = g0[i];
    if (i == 0) bar_ctr = 0;
}

__global__ void __launch_bounds__(NTHR, 1) lif_persistent_kernel(
    const float* __restrict__ x_in,    // [T, N]
    const float* __restrict__ w,       // [N, N] row-major
    const float* __restrict__ v_rest,  // [N]
    const float* __restrict__ tau_m,   // [N]
    const float* __restrict__ tau_g,   // [N]
    const float* __restrict__ pre_c_p, // [1]
    const float* __restrict__ post_c_p,// [1]
    const float* __restrict__ v0,      // [N]
    const float* __restrict__ g0,      // [N]
    float* __restrict__ out)           // [2, T, N]
{
    const int tid  = threadIdx.x;
    const int cta  = blockIdx.x;
    const int lane = tid & 31;
    const int warp = tid >> 5;
    const int row0 = cta * ROWS;
    const int col0 = tid * CPT;

    __shared__ float sh_part[2][8][ROWS];

    // ---- one-time: this CTA's 16 w rows in REGISTERS, packed as f32x2 ----
    unsigned long long wp2[ROWS][4];     // 64 x u64 = 128 fp32 regs
    #pragma unroll
    for (int r = 0; r < ROWS; r++) {
        const float4* wp = reinterpret_cast<const float4*>(
            w + (size_t)(row0 + r) * NN + col0);
        float4 a = wp[0], b = wp[1];
        wp2[r][0] = pack2(a.x, a.y);
        wp2[r][1] = pack2(a.z, a.w);
        wp2[r][2] = pack2(b.x, b.y);
        wp2[r][3] = pack2(b.z, b.w);
    }

    // ---- per-neuron state in the first 16 threads' registers ----
    const float pre_c  = pre_c_p[0];
    const float post_c = post_c_p[0];
    float my_v = 0.f, my_g = 0.f, my_vrest = 0.f, my_taum = 1.f, my_taug = 1.f;
    float x_next = 0.f;
    if (tid < ROWS) {
        int i = row0 + tid;
        my_v     = v0[i];
        my_g     = g0[i];
        my_vrest = v_rest[i];
        my_taum  = tau_m[i];
        my_taug  = tau_g[i];
        x_next   = __ldcs(&x_in[i]);   // prefetch x for t=0
    }
    __syncthreads();

    for (int t = 0; t < T_STEPS; t++) {
        const int par = t & 1;

        // ---- wait until all CTAs finished step t-1 (counter = NCTA*t) ----
        // R5-proven spin: plain .cg load, no per-iteration ordering cost.
        if (t > 0) {
            if (tid == 0) {
                const unsigned target = (unsigned)(NCTA * t);
                unsigned c;
                do {
                    asm volatile("ld.global.cg.u32 %0, [%1];"
                                 : "=r"(c) : "l"(&bar_ctr));
                } while (c < target);
            }
            __syncthreads();
        }

        // ---- load g for this step (L1-bypass; written by other SMs) ----
        unsigned long long gp2[4];
        {
            const float4 ga = __ldcg(reinterpret_cast<const float4*>(g_buf[par] + col0));
            const float4 gb = __ldcg(reinterpret_cast<const float4*>(g_buf[par] + col0 + 4));
            gp2[0] = pack2(ga.x, ga.y);
            gp2[1] = pack2(ga.z, ga.w);
            gp2[2] = pack2(gb.x, gb.y);
            gp2[3] = pack2(gb.z, gb.w);
        }

        // ---- prefetch next step's x (hides HBM latency) ----
        float x_cur = x_next;
        if (tid < ROWS && t + 1 < T_STEPS) {
            x_next = __ldcs(&x_in[(size_t)(t + 1) * NN + row0 + tid]);
        }

        // ---- matvec partials: 16 rows x 4 packed f32x2 FMAs per row ----
        float acc[ROWS];
        #pragma unroll
        for (int r = 0; r < ROWS; r++) {
            unsigned long long s2 = mul2(wp2[r][0], gp2[0]);
            s2 = fma2(wp2[r][1], gp2[1], s2);
            s2 = fma2(wp2[r][2], gp2[2], s2);
            s2 = fma2(wp2[r][3], gp2[3], s2);
            float lo, hi;
            unpack2(s2, lo, hi);
            acc[r] = lo + hi;
        }

        // ---- intra-warp folding reduction: 16 rows over 32 lanes, 16 SHFLs ----
        #pragma unroll
        for (int r = 0; r < 8; r++) {
            bool hi = (lane & 16) != 0;
            float send = hi ? acc[r] : acc[r + 8];
            float keep = hi ? acc[r + 8] : acc[r];
            acc[r] = keep + __shfl_xor_sync(0xffffffffu, send, 16);
        }
        #pragma unroll
        for (int r = 0; r < 4; r++) {
            bool hi = (lane & 8) != 0;
            float send = hi ? acc[r] : acc[r + 4];
            float keep = hi ? acc[r + 4] : acc[r];
            acc[r] = keep + __shfl_xor_sync(0xffffffffu, send, 8);
        }
        #pragma unroll
        for (int r = 0; r < 2; r++) {
            bool hi = (lane & 4) != 0;
            float send = hi ? acc[r] : acc[r + 2];
            float keep = hi ? acc[r + 2] : acc[r];
            acc[r] = keep + __shfl_xor_sync(0xffffffffu, send, 4);
        }
        {
            bool hi = (lane & 2) != 0;
            float send = hi ? acc[0] : acc[1];
            float keep = hi ? acc[1] : acc[0];
            acc[0] = keep + __shfl_xor_sync(0xffffffffu, send, 2);
        }
        acc[0] += __shfl_xor_sync(0xffffffffu, acc[0], 1);

        if ((lane & 1) == 0) sh_part[par][warp][lane >> 1] = acc[0];
        __syncthreads();

        // ---- LIF update: ONLY what g_new needs before the publish ----
        float v_new = 0.f, vpre = 0.f;
        if (tid < ROWS) {
            float y = 0.f;
            #pragma unroll
            for (int wq = 0; wq < 8; wq++) y += sh_part[par][wq][tid];
            y += x_cur;

            float I = post_c / (1.f + expf(-pre_c * y));
            float gd = my_g - my_g / my_taug;
            float v  = my_v + ((my_vrest - my_v) + I) / my_taum;
            bool spk = (v >= 30.f);
            vpre  = v;                        // pre-reset v (for soft sigmoid)
            v_new = spk ? my_vrest : v;
            float g_new = spk ? 1.f : gd;
            my_v = v_new;
            my_g = g_new;

            __stcg(&g_buf[(t + 1) & 1][row0 + tid], g_new);   // publish g
        }

        // Release: warp 0's fence covers the 16 g stores, then tid0 arrives.
        if (warp == 0) __threadfence();
        if (tid == 0) atomicAdd(&bar_ctr, 1u);

        // Everything below is off the inter-CTA critical path:
        // the soft-spike sigmoid and both DRAM trace stores.
        if (tid < ROWS) {
            float soft = 1.f / (1.f + expf(-(vpre - 30.f)));
            int i = row0 + tid;
            __stcs(&out[(size_t)t * NN + i], v_new);
            __stcs(&out[(size_t)T_STEPS * NN + (size_t)t * NN + i], soft);
        }
        // No trailing CTA barrier: next iteration's poll + __syncthreads gates
        // every warp; g and sh_part are parity double-buffered.
    }
}

extern "C" void kernel_launch(void* const* d_in, const int* in_sizes, int n_in,
                              void* d_out, int out_size) {
    (void)in_sizes; (void)n_in; (void)out_size;
    const float* x_in   = (const float*)d_in[0];
    const float* w      = (const float*)d_in[1];
    const float* v_rest = (const float*)d_in[2];
    const float* tau_m  = (const float*)d_in[3];
    const float* tau_g  = (const float*)d_in[4];
    const float* pre_c  = (const float*)d_in[5];
    const float* post_c = (const float*)d_in[6];
    const float* v0     = (const float*)d_in[7];
    const float* g0     = (const float*)d_in[8];
    float* out = (float*)d_out;

    lif_init_kernel<<<(NN + 255) / 256, 256>>>(g0);
    lif_persistent_kernel<<<NCTA, NTHR>>>(x_in, w, v_rest, tau_m, tau_g,
                                          pre_c, post_c, v0, g0, out);
}